// round 12
// baseline (speedup 1.0000x reference)
#include <cuda_runtime.h>
#include <cuda_fp16.h>
#include <math_constants.h>

// SumLayer: out[nids[n], b] = log(clip(sum_c params[pids[n,c]] * exp(em[cids[n,c],b]), 1e-10))
//
// Fused persistent kernel, batch split in halves of 128:
//   Stage A: all blocks: phase1 half0 (scratch = half(exp(em)))
//   Stage B: 2/5 blocks phase1 half1 (DRAM)  ||  3/5 blocks phase2 half0 (LTS)
//   Stage C: all blocks: phase2 half1
// Phase 2 keeps full-width uint4 gathers by packing 2 nodes per warp
// (lanes 0-15 node A, 16-31 node B) -> same instruction/byte efficiency as
// the 47us standalone phase 2. Grid sized by occupancy API (co-resident);
// software grid barrier = monotone generation counter (wrap-safe).

#define FAST_C 16
#define FAST_B 256
#define CH_SIZE_MAX 131072
#define NODES_PER_GROUP 16     // 8 warps x 2 nodes

// 64 MB scratch: exp(em) as half. Row = 256 halves = 32 uint4.
__device__ uint4 g_scratch[(size_t)CH_SIZE_MAX * 32];
__device__ unsigned g_bar;     // monotone barrier counter (never reset)

// ---- packed helpers ----
__device__ __forceinline__ unsigned int h2_as_u32(__half2 h)
{
    unsigned int u;
    *(__half2*)&u = h;
    return u;
}

__device__ __forceinline__ unsigned long long h2_to_f32x2(unsigned int h)
{
    unsigned long long f;
    asm("{\n\t"
        ".reg .f16 a, b;\n\t"
        ".reg .f32 fa, fb;\n\t"
        "mov.b32 {a, b}, %1;\n\t"
        "cvt.f32.f16 fa, a;\n\t"
        "cvt.f32.f16 fb, b;\n\t"
        "mov.b64 %0, {fa, fb};\n\t"
        "}" : "=l"(f) : "r"(h));
    return f;
}

__device__ __forceinline__ void fma_f32x2(unsigned long long& acc,
                                          unsigned long long a,
                                          unsigned long long b)
{
    asm("fma.rn.f32x2 %0, %1, %2, %3;" : "=l"(acc) : "l"(a), "l"(b), "l"(acc));
}

// ---- grid barrier: generation-counting, wrap-safe, reusable across replays ----
__device__ __forceinline__ void grid_barrier(unsigned nblocks)
{
    __syncthreads();
    if (threadIdx.x == 0) {
        __threadfence();
        unsigned my = atomicAdd(&g_bar, 1u);
        unsigned target = (my / nblocks + 1u) * nblocks;
        while ((int)(*(volatile unsigned*)&g_bar - target) < 0) {
            __nanosleep(64);
        }
        __threadfence();
    }
    __syncthreads();
}

// ---- phase 1 over one batch half (128 elems): 8 floats -> 1 uint4 of halves ----
__device__ __forceinline__ void p1_half(const float4* __restrict__ em4,
                                        int rows, int h, int worker, int nworkers)
{
    const int total = rows << 4;                  // rows * 16 uint4 per half-row
    for (int idx = worker * 256 + threadIdx.x; idx < total; idx += nworkers * 256) {
        const int row = idx >> 4, q = idx & 15;
        const int ebase = (row << 6) + (h << 5) + (q << 1);
        float4 e0 = __ldcs(&em4[ebase + 0]);
        float4 e1 = __ldcs(&em4[ebase + 1]);
        uint4 u;
        u.x = h2_as_u32(__floats2half2_rn(__expf(e0.x), __expf(e0.y)));
        u.y = h2_as_u32(__floats2half2_rn(__expf(e0.z), __expf(e0.w)));
        u.z = h2_as_u32(__floats2half2_rn(__expf(e1.x), __expf(e1.y)));
        u.w = h2_as_u32(__floats2half2_rn(__expf(e1.z), __expf(e1.w)));
        g_scratch[(row << 5) + (h << 4) + q] = u;  // stays L2-resident
    }
}

// ---- phase 2 over one batch half: 2 nodes per warp, uint4 gathers ----
__device__ __forceinline__ void p2_half(const float* __restrict__ params,
                                        const int* __restrict__ nids,
                                        const int* __restrict__ cids,
                                        const int* __restrict__ pids,
                                        float* __restrict__ out,
                                        int h, int worker, int nworkers, int ngroups,
                                        int* s_row_all, float2* s_w_all)
{
    const int w    = threadIdx.x >> 5;
    const int lane = threadIdx.x & 31;
    const int sub  = lane >> 4;        // node within warp pair: 0/1
    const int q    = lane & 15;        // uint4 quarter within half-row
    int*    s_row = s_row_all + (w << 5);   // [2][16]
    float2* s_w   = s_w_all   + (w << 5);
    const uint4* __restrict__ sc = g_scratch;

    for (int g = worker; g < ngroups; g += nworkers) {
        const int node = (g << 4) + (w << 1) + sub;
        // All 32 lanes: one (cid,pid) each for (my node, child q).
        s_row[lane] = cids[(node << 4) + q] << 5;           // uint4 row base
        const float wv = params[pids[(node << 4) + q]];
        s_w[lane] = make_float2(wv, wv);
        __syncwarp();

        const int hq = (h << 4) + q;
        unsigned long long a0 = 0, a1 = 0, a2 = 0, a3 = 0;  // 8 fp32 accum
#pragma unroll
        for (int ch = 0; ch < FAST_C; ch += 4) {
            uint4 v[4];
#pragma unroll
            for (int c = 0; c < 4; c++) {
                v[c] = sc[s_row[(sub << 4) + ch + c] + hq];
            }
#pragma unroll
            for (int c = 0; c < 4; c++) {
                const unsigned long long wp =
                    *(const unsigned long long*)&s_w[(sub << 4) + ch + c];
                fma_f32x2(a0, h2_to_f32x2(v[c].x), wp);
                fma_f32x2(a1, h2_to_f32x2(v[c].y), wp);
                fma_f32x2(a2, h2_to_f32x2(v[c].z), wp);
                fma_f32x2(a3, h2_to_f32x2(v[c].w), wp);
            }
        }

        const float2 s0 = *(float2*)&a0, s1 = *(float2*)&a1;
        const float2 s2 = *(float2*)&a2, s3 = *(float2*)&a3;
        float4 o0, o1;
        o0.x = __logf(fmaxf(s0.x, 1e-10f));
        o0.y = __logf(fmaxf(s0.y, 1e-10f));
        o0.z = __logf(fmaxf(s1.x, 1e-10f));
        o0.w = __logf(fmaxf(s1.y, 1e-10f));
        o1.x = __logf(fmaxf(s2.x, 1e-10f));
        o1.y = __logf(fmaxf(s2.y, 1e-10f));
        o1.z = __logf(fmaxf(s3.x, 1e-10f));
        o1.w = __logf(fmaxf(s3.y, 1e-10f));

        float4* orow = (float4*)out + ((long long)nids[node] << 6) + (h << 5) + (q << 1);
        __stcs(&orow[0], o0);
        __stcs(&orow[1], o1);
        __syncwarp();                 // protect s_row/s_w before next iteration
    }
}

// ---- fused persistent kernel ----
__global__ __launch_bounds__(256, 5) void sum_layer_fused(
    const float4* __restrict__ em4,
    const float*  __restrict__ params,
    const int*    __restrict__ nids,
    const int*    __restrict__ cids,
    const int*    __restrict__ pids,
    float*        __restrict__ out,
    int rows, int ngroups, int nblocks, int g1)
{
    __shared__ int    s_row_all[8 * 32];
    __shared__ float2 s_w_all[8 * 32];

    const int bid = blockIdx.x;

    // Stage A: phase 1, half 0, all blocks
    p1_half(em4, rows, 0, bid, nblocks);
    grid_barrier((unsigned)nblocks);

    // Stage B: overlap p1(half1, DRAM-bound) with p2(half0, LTS-bound)
    if (bid < g1) {
        p1_half(em4, rows, 1, bid, g1);
    } else {
        p2_half(params, nids, cids, pids, out, 0,
                bid - g1, nblocks - g1, ngroups, s_row_all, s_w_all);
    }
    grid_barrier((unsigned)nblocks);

    // Stage C: phase 2, half 1, all blocks
    p2_half(params, nids, cids, pids, out, 1,
            bid, nblocks, ngroups, s_row_all, s_w_all);
}

// ---------------- Generic fallback (exact, single kernel) ----------------
__global__ void sum_layer_generic(
    const float* __restrict__ em,
    const float* __restrict__ params,
    const int*   __restrict__ nids,
    const int*   __restrict__ cids,
    const int*   __restrict__ pids,
    float*       __restrict__ out,
    int n_nodes, int C, int B)
{
    long long idx = (long long)blockIdx.x * blockDim.x + threadIdx.x;
    long long total = (long long)n_nodes * B;
    if (idx >= total) return;
    int node = (int)(idx / B);
    int b    = (int)(idx % B);

    float m = -CUDART_INF_F;
    for (int c = 0; c < C; c++) {
        float v = em[(long long)cids[node * C + c] * B + b];
        m = fmaxf(m, v);
    }
    float s = 0.f;
    for (int c = 0; c < C; c++) {
        float v = em[(long long)cids[node * C + c] * B + b];
        s += __expf(v - m) * params[pids[node * C + c]];
    }
    out[(long long)nids[node] * B + b] = __logf(fmaxf(s, 1e-10f)) + m;
}

extern "C" void kernel_launch(void* const* d_in, const int* in_sizes, int n_in,
                              void* d_out, int out_size)
{
    // metadata order: node_mars, element_mars, params, nids, cids, pids
    const float* em     = (const float*)d_in[1];
    const float* params = (const float*)d_in[2];
    const int*   nids   = (const int*)d_in[3];
    const int*   cids   = (const int*)d_in[4];
    const int*   pids   = (const int*)d_in[5];
    float*       out    = (float*)d_out;

    const int n_nodes = in_sizes[3];
    const int C       = in_sizes[4] / n_nodes;
    const int B       = in_sizes[0] / n_nodes;
    const int ch_size = in_sizes[1] / B;      // element_mars rows

    int bpm = 0, sms = 0, dev = 0;
    cudaGetDevice(&dev);
    cudaOccupancyMaxActiveBlocksPerMultiprocessor(&bpm, sum_layer_fused, 256, 0);
    cudaDeviceGetAttribute(&sms, cudaDevAttrMultiProcessorCount, dev);

    if (C == FAST_C && B == FAST_B && (n_nodes % NODES_PER_GROUP) == 0 &&
        ch_size <= CH_SIZE_MAX && bpm >= 1 && sms >= 1) {
        const int nblocks = bpm * sms;             // guaranteed co-resident
        const int ngroups = n_nodes / NODES_PER_GROUP;
        int g1 = (2 * nblocks) / 5;                // stage-B phase-1 workers
        if (g1 < 1) g1 = 1;
        if (g1 >= nblocks) g1 = nblocks - 1;
        sum_layer_fused<<<nblocks, 256>>>((const float4*)em, params, nids, cids,
                                          pids, out, ch_size, ngroups, nblocks, g1);
    } else {
        const long long total = (long long)n_nodes * B;
        const int threads = 256;
        const int grid = (int)((total + threads - 1) / threads);
        sum_layer_generic<<<grid, threads>>>(em, params, nids, cids, pids, out,
                                             n_nodes, C, B);
    }
}

// round 13
// speedup vs baseline: 1.4782x; 1.4782x over previous
#include <cuda_runtime.h>
#include <cuda_fp16.h>
#include <math_constants.h>

// SumLayer: out[nids[n], b] = log(clip(sum_c params[pids[n,c]] * exp(em[cids[n,c],b]), 1e-10))
//
// Two-phase (proven structure, R9 = 78.3us):
//   Phase 1: g_scratch = half(exp(em)) -- exp once per table entry (8x fewer
//            MUFU); fp16 table = 64MB, L2-resident. DRAM-streaming bound.
//   Phase 2: one warp per node; uint4 gathers (8 half elems/child/thread),
//            packed f32x2 FMA, one log/elem. At the LTS (~6300 B/cyc) wall.
// R12 change: phase 2 launch_bounds(256,6) -> ~62% occupancy to cover
// L2-hit latency (issue was 42% at occ 52%).

#define FAST_C 16
#define FAST_B 256
#define NPB 8            // nodes per 256-thread block (1 warp per node)
#define CHUNK 4

#define CH_SIZE_MAX 131072
// 64 MB scratch: exp(em) as half, viewed as uint4 (8 halves) for 16B I/O.
__device__ uint4 g_scratch[(size_t)CH_SIZE_MAX * FAST_B / 8];

// half2 -> packed float2 (as 64-bit), then packed fma.
__device__ __forceinline__ unsigned long long h2_to_f32x2(unsigned int h)
{
    unsigned long long f;
    asm("{\n\t"
        ".reg .f16 a, b;\n\t"
        ".reg .f32 fa, fb;\n\t"
        "mov.b32 {a, b}, %1;\n\t"
        "cvt.f32.f16 fa, a;\n\t"
        "cvt.f32.f16 fb, b;\n\t"
        "mov.b64 %0, {fa, fb};\n\t"
        "}" : "=l"(f) : "r"(h));
    return f;
}

__device__ __forceinline__ void fma_f32x2(unsigned long long& acc,
                                          unsigned long long a,
                                          unsigned long long b)
{
    asm("fma.rn.f32x2 %0, %1, %2, %3;" : "=l"(acc) : "l"(a), "l"(b), "l"(acc));
}

// ---------------- Phase 1: exp + fp16 quantize ----------------
__global__ __launch_bounds__(256) void exp_quant_kernel(
    const float4* __restrict__ em4, int n4)
{
    int i = blockIdx.x * 256 + threadIdx.x;
    if (i >= n4) return;
    float4 v = __ldcs(&em4[i]);            // read-once: evict-first
    __half2 h0 = __floats2half2_rn(__expf(v.x), __expf(v.y));
    __half2 h1 = __floats2half2_rn(__expf(v.z), __expf(v.w));
    uint2 u;
    ((__half2*)&u)[0] = h0;
    ((__half2*)&u)[1] = h1;
    ((uint2*)g_scratch)[i] = u;            // normal store: stays L2-resident
}

// ---------------- Phase 2: gather + weighted sum + log ----------------
__global__ __launch_bounds__(256, 6) void sum_layer_fast(
    const float* __restrict__ params,  // [N_PARAMS]
    const int*   __restrict__ nids,    // [N]
    const int*   __restrict__ cids,    // [N, 16]
    const int*   __restrict__ pids,    // [N, 16]
    float*       __restrict__ out)     // [N, 256]
{
    const int w    = threadIdx.x >> 5;        // warp = node within block: 0..7
    const int lane = threadIdx.x & 31;        // 8 batch elems each (one uint4)
    const int node = (blockIdx.x << 3) + w;

    __shared__ int    s_row[NPB][FAST_C];     // cid * 32 (uint4 row offset)
    __shared__ float2 s_w[NPB][FAST_C];       // (w, w) packed for f32x2 FMA

    // Warp-private setup: lanes 0..15 load this node's children.
    if (lane < FAST_C) {
        s_row[w][lane] = cids[(node << 4) + lane] << 5;  // row * 256 halves / 8
        const float wv = params[pids[(node << 4) + lane]];
        s_w[w][lane] = make_float2(wv, wv);
    }
    __syncwarp();

    const uint4* __restrict__ sc = (const uint4*)g_scratch;

    unsigned long long a0 = 0, a1 = 0, a2 = 0, a3 = 0;   // 4 x packed float2

#pragma unroll
    for (int ch = 0; ch < FAST_C; ch += CHUNK) {
        uint4 v[CHUNK];
#pragma unroll
        for (int c = 0; c < CHUNK; c++) {
            v[c] = sc[s_row[w][ch + c] + lane];
        }
#pragma unroll
        for (int c = 0; c < CHUNK; c++) {
            const unsigned long long wp =
                *(const unsigned long long*)&s_w[w][ch + c];   // LDS.64 bcast
            fma_f32x2(a0, h2_to_f32x2(v[c].x), wp);
            fma_f32x2(a1, h2_to_f32x2(v[c].y), wp);
            fma_f32x2(a2, h2_to_f32x2(v[c].z), wp);
            fma_f32x2(a3, h2_to_f32x2(v[c].w), wp);
        }
    }

    float2 s0 = *(float2*)&a0, s1 = *(float2*)&a1;
    float2 s2 = *(float2*)&a2, s3 = *(float2*)&a3;

    float4 o0, o1;
    o0.x = __logf(fmaxf(s0.x, 1e-10f));
    o0.y = __logf(fmaxf(s0.y, 1e-10f));
    o0.z = __logf(fmaxf(s1.x, 1e-10f));
    o0.w = __logf(fmaxf(s1.y, 1e-10f));
    o1.x = __logf(fmaxf(s2.x, 1e-10f));
    o1.y = __logf(fmaxf(s2.y, 1e-10f));
    o1.z = __logf(fmaxf(s3.x, 1e-10f));
    o1.w = __logf(fmaxf(s3.y, 1e-10f));

    float4* orow = (float4*)out + ((long long)nids[node] << 6);
    __stcs(&orow[lane * 2 + 0], o0);
    __stcs(&orow[lane * 2 + 1], o1);
}

// ---------------- Generic fallback (exact, single kernel) ----------------
__global__ void sum_layer_generic(
    const float* __restrict__ em,
    const float* __restrict__ params,
    const int*   __restrict__ nids,
    const int*   __restrict__ cids,
    const int*   __restrict__ pids,
    float*       __restrict__ out,
    int n_nodes, int C, int B)
{
    long long idx = (long long)blockIdx.x * blockDim.x + threadIdx.x;
    long long total = (long long)n_nodes * B;
    if (idx >= total) return;
    int node = (int)(idx / B);
    int b    = (int)(idx % B);

    float m = -CUDART_INF_F;
    for (int c = 0; c < C; c++) {
        float v = em[(long long)cids[node * C + c] * B + b];
        m = fmaxf(m, v);
    }
    float s = 0.f;
    for (int c = 0; c < C; c++) {
        float v = em[(long long)cids[node * C + c] * B + b];
        s += __expf(v - m) * params[pids[node * C + c]];
    }
    out[(long long)nids[node] * B + b] = __logf(fmaxf(s, 1e-10f)) + m;
}

extern "C" void kernel_launch(void* const* d_in, const int* in_sizes, int n_in,
                              void* d_out, int out_size)
{
    // metadata order: node_mars, element_mars, params, nids, cids, pids
    const float* em     = (const float*)d_in[1];
    const float* params = (const float*)d_in[2];
    const int*   nids   = (const int*)d_in[3];
    const int*   cids   = (const int*)d_in[4];
    const int*   pids   = (const int*)d_in[5];
    float*       out    = (float*)d_out;

    const int n_nodes = in_sizes[3];
    const int C       = in_sizes[4] / n_nodes;
    const int B       = in_sizes[0] / n_nodes;
    const int ch_size = in_sizes[1] / B;      // element_mars rows

    if (C == FAST_C && B == FAST_B && (n_nodes % NPB) == 0 &&
        ch_size <= CH_SIZE_MAX && (ch_size * FAST_B) % 8 == 0) {
        const int n4 = ch_size * FAST_B / 4;
        exp_quant_kernel<<<(n4 + 255) / 256, 256>>>((const float4*)em, n4);
        sum_layer_fast<<<n_nodes / NPB, 256>>>(params, nids, cids, pids, out);
    } else {
        const long long total = (long long)n_nodes * B;
        const int threads = 256;
        const int grid = (int)((total + threads - 1) / threads);
        sum_layer_generic<<<grid, threads>>>(em, params, nids, cids, pids, out,
                                             n_nodes, C, B);
    }
}

// round 14
// speedup vs baseline: 1.5621x; 1.0567x over previous
#include <cuda_runtime.h>
#include <cuda_fp16.h>
#include <math_constants.h>

// SumLayer: out[nids[n], b] = log(clip(sum_c params[pids[n,c]] * exp(em[cids[n,c],b]), 1e-10))
//
// Two-phase:
//   Phase 1: g_scratch = half(exp(em)) -- exp once per table entry; fp16
//            table = 64MB, L2-resident. DRAM-streaming bound (192MB
//            compulsory). Persistent grid, 32B/iter (2x LDG.128 + STG.128).
//   Phase 2: one warp per node; uint4 gathers (8 half elems/child/thread),
//            packed f32x2 FMA, one log/elem. AT THE LTS WALL (~591MB of
//            L1<->L2 traffic at ~6300 B/cyc = measured 46us). FROZEN.

#define FAST_C 16
#define FAST_B 256
#define NPB 8            // nodes per 256-thread block (1 warp per node)
#define CHUNK 4

#define CH_SIZE_MAX 131072
// 64 MB scratch: exp(em) as half, viewed as uint4 (8 halves) for 16B I/O.
__device__ uint4 g_scratch[(size_t)CH_SIZE_MAX * FAST_B / 8];

// half2 -> packed float2 (as 64-bit), then packed fma.
__device__ __forceinline__ unsigned long long h2_to_f32x2(unsigned int h)
{
    unsigned long long f;
    asm("{\n\t"
        ".reg .f16 a, b;\n\t"
        ".reg .f32 fa, fb;\n\t"
        "mov.b32 {a, b}, %1;\n\t"
        "cvt.f32.f16 fa, a;\n\t"
        "cvt.f32.f16 fb, b;\n\t"
        "mov.b64 %0, {fa, fb};\n\t"
        "}" : "=l"(f) : "r"(h));
    return f;
}

__device__ __forceinline__ void fma_f32x2(unsigned long long& acc,
                                          unsigned long long a,
                                          unsigned long long b)
{
    asm("fma.rn.f32x2 %0, %1, %2, %3;" : "=l"(acc) : "l"(a), "l"(b), "l"(acc));
}

__device__ __forceinline__ unsigned int h2_as_u32(__half2 h)
{
    unsigned int u;
    *(__half2*)&u = h;
    return u;
}

// ---------------- Phase 1: exp + fp16 quantize (persistent, 32B/iter) ------
__global__ __launch_bounds__(256) void exp_quant_kernel(
    const float4* __restrict__ em4, int n8)   // n8 = total elems / 8
{
    const int stride = gridDim.x * 256;
    for (int i = blockIdx.x * 256 + threadIdx.x; i < n8; i += stride) {
        float4 e0 = __ldcs(&em4[2 * i + 0]);
        float4 e1 = __ldcs(&em4[2 * i + 1]);
        uint4 u;
        u.x = h2_as_u32(__floats2half2_rn(__expf(e0.x), __expf(e0.y)));
        u.y = h2_as_u32(__floats2half2_rn(__expf(e0.z), __expf(e0.w)));
        u.z = h2_as_u32(__floats2half2_rn(__expf(e1.x), __expf(e1.y)));
        u.w = h2_as_u32(__floats2half2_rn(__expf(e1.z), __expf(e1.w)));
        g_scratch[i] = u;                      // normal store: L2-resident
    }
}

// ---------------- Phase 2: gather + weighted sum + log (FROZEN) ------------
__global__ __launch_bounds__(256, 6) void sum_layer_fast(
    const float* __restrict__ params,  // [N_PARAMS]
    const int*   __restrict__ nids,    // [N]
    const int*   __restrict__ cids,    // [N, 16]
    const int*   __restrict__ pids,    // [N, 16]
    float*       __restrict__ out)     // [N, 256]
{
    const int w    = threadIdx.x >> 5;        // warp = node within block: 0..7
    const int lane = threadIdx.x & 31;        // 8 batch elems each (one uint4)
    const int node = (blockIdx.x << 3) + w;

    __shared__ int    s_row[NPB][FAST_C];     // cid * 32 (uint4 row offset)
    __shared__ float2 s_w[NPB][FAST_C];       // (w, w) packed for f32x2 FMA

    // Warp-private setup: lanes 0..15 load this node's children.
    if (lane < FAST_C) {
        s_row[w][lane] = cids[(node << 4) + lane] << 5;  // row * 256 halves / 8
        const float wv = params[pids[(node << 4) + lane]];
        s_w[w][lane] = make_float2(wv, wv);
    }
    __syncwarp();

    const uint4* __restrict__ sc = (const uint4*)g_scratch;

    unsigned long long a0 = 0, a1 = 0, a2 = 0, a3 = 0;   // 4 x packed float2

#pragma unroll
    for (int ch = 0; ch < FAST_C; ch += CHUNK) {
        uint4 v[CHUNK];
#pragma unroll
        for (int c = 0; c < CHUNK; c++) {
            v[c] = sc[s_row[w][ch + c] + lane];
        }
#pragma unroll
        for (int c = 0; c < CHUNK; c++) {
            const unsigned long long wp =
                *(const unsigned long long*)&s_w[w][ch + c];   // LDS.64 bcast
            fma_f32x2(a0, h2_to_f32x2(v[c].x), wp);
            fma_f32x2(a1, h2_to_f32x2(v[c].y), wp);
            fma_f32x2(a2, h2_to_f32x2(v[c].z), wp);
            fma_f32x2(a3, h2_to_f32x2(v[c].w), wp);
        }
    }

    float2 s0 = *(float2*)&a0, s1 = *(float2*)&a1;
    float2 s2 = *(float2*)&a2, s3 = *(float2*)&a3;

    float4 o0, o1;
    o0.x = __logf(fmaxf(s0.x, 1e-10f));
    o0.y = __logf(fmaxf(s0.y, 1e-10f));
    o0.z = __logf(fmaxf(s1.x, 1e-10f));
    o0.w = __logf(fmaxf(s1.y, 1e-10f));
    o1.x = __logf(fmaxf(s2.x, 1e-10f));
    o1.y = __logf(fmaxf(s2.y, 1e-10f));
    o1.z = __logf(fmaxf(s3.x, 1e-10f));
    o1.w = __logf(fmaxf(s3.y, 1e-10f));

    float4* orow = (float4*)out + ((long long)nids[node] << 6);
    __stcs(&orow[lane * 2 + 0], o0);
    __stcs(&orow[lane * 2 + 1], o1);
}

// ---------------- Generic fallback (exact, single kernel) ----------------
__global__ void sum_layer_generic(
    const float* __restrict__ em,
    const float* __restrict__ params,
    const int*   __restrict__ nids,
    const int*   __restrict__ cids,
    const int*   __restrict__ pids,
    float*       __restrict__ out,
    int n_nodes, int C, int B)
{
    long long idx = (long long)blockIdx.x * blockDim.x + threadIdx.x;
    long long total = (long long)n_nodes * B;
    if (idx >= total) return;
    int node = (int)(idx / B);
    int b    = (int)(idx % B);

    float m = -CUDART_INF_F;
    for (int c = 0; c < C; c++) {
        float v = em[(long long)cids[node * C + c] * B + b];
        m = fmaxf(m, v);
    }
    float s = 0.f;
    for (int c = 0; c < C; c++) {
        float v = em[(long long)cids[node * C + c] * B + b];
        s += __expf(v - m) * params[pids[node * C + c]];
    }
    out[(long long)nids[node] * B + b] = __logf(fmaxf(s, 1e-10f)) + m;
}

extern "C" void kernel_launch(void* const* d_in, const int* in_sizes, int n_in,
                              void* d_out, int out_size)
{
    // metadata order: node_mars, element_mars, params, nids, cids, pids
    const float* em     = (const float*)d_in[1];
    const float* params = (const float*)d_in[2];
    const int*   nids   = (const int*)d_in[3];
    const int*   cids   = (const int*)d_in[4];
    const int*   pids   = (const int*)d_in[5];
    float*       out    = (float*)d_out;

    const int n_nodes = in_sizes[3];
    const int C       = in_sizes[4] / n_nodes;
    const int B       = in_sizes[0] / n_nodes;
    const int ch_size = in_sizes[1] / B;      // element_mars rows

    if (C == FAST_C && B == FAST_B && (n_nodes % NPB) == 0 &&
        ch_size <= CH_SIZE_MAX && (ch_size * FAST_B) % 8 == 0) {
        const int n8 = ch_size * FAST_B / 8;
        int sms = 148, dev = 0;
        cudaGetDevice(&dev);
        cudaDeviceGetAttribute(&sms, cudaDevAttrMultiProcessorCount, dev);
        const int p1_blocks = sms * 8;         // persistent full waves
        exp_quant_kernel<<<p1_blocks, 256>>>((const float4*)em, n8);
        sum_layer_fast<<<n_nodes / NPB, 256>>>(params, nids, cids, pids, out);
    } else {
        const long long total = (long long)n_nodes * B;
        const int threads = 256;
        const int grid = (int)((total + threads - 1) / threads);
        sum_layer_generic<<<grid, threads>>>(em, params, nids, cids, pids, out,
                                             n_nodes, C, B);
    }
}